// round 4
// baseline (speedup 1.0000x reference)
#include <cuda_runtime.h>

// Problem constants (fixed by reference setup_inputs)
#define Hh     32
#define EPB    4          // batch elements per block (== number of warps)
#define TIN    999        // teacher-forced steps
#define STEPS  1999       // TIN + future(1000)
#define BATCH  1024

typedef unsigned long long u64;

// Packed 2xfp32 FMA (sm_103a FFMA2) — lane-wise: d.lo = a.lo*b.lo+c.lo, d.hi likewise
__device__ __forceinline__ u64 fma2(u64 a, u64 b, u64 c) {
    u64 d;
    asm("fma.rn.f32x2 %0, %1, %2, %3;" : "=l"(d) : "l"(a), "l"(b), "l"(c));
    return d;
}
__device__ __forceinline__ float f2lo(u64 a) { return __uint_as_float((unsigned)a); }
__device__ __forceinline__ float f2hi(u64 a) { return __uint_as_float((unsigned)(a >> 32)); }

__device__ __forceinline__ float ex2a(float x) { float y; asm("ex2.approx.f32 %0, %1;" : "=f"(y) : "f"(x)); return y; }
__device__ __forceinline__ float rcpa(float x) { float y; asm("rcp.approx.f32 %0, %1;" : "=f"(y) : "f"(x)); return y; }

// sigmoid(x) = 1/(1 + 2^(-x*log2e)); accurate ~1e-7, saturates correctly at +-inf
__device__ __forceinline__ float sigm(float x) {
    return rcpa(1.0f + ex2a(-1.4426950408889634f * x));
}
// tanh(x) = 1 - 2/(2^(2x*log2e) + 1); accurate ~1e-7 (avoids tanh.approx ~1e-3 error)
__device__ __forceinline__ float tanh_(float x) {
    return fmaf(-2.0f, rcpa(1.0f + ex2a(2.8853900817779268f * x)), 1.0f);
}

__global__ __launch_bounds__(128) void lstm_seq_kernel(
    const float* __restrict__ input,                                   // [B, TIN]
    const float* __restrict__ W_ih1, const float* __restrict__ W_hh1,  // [4H,1], [4H,H]
    const float* __restrict__ b_ih1, const float* __restrict__ b_hh1,  // [4H]
    const float* __restrict__ W_ih2, const float* __restrict__ W_hh2,  // [4H,H], [4H,H]
    const float* __restrict__ b_ih2, const float* __restrict__ b_hh2,  // [4H]
    const float* __restrict__ W_lin, const float* __restrict__ b_lin,  // [1,H], [1]
    float* __restrict__ out)                                           // [B, STEPS]
{
    __shared__ float sh_in[EPB][TIN];                       // staged input rows (~16KB)
    __shared__ __align__(16) float sh_h1[EPB][Hh];
    __shared__ __align__(16) float sh_h2[EPB][Hh];
    __shared__ float sh_z[EPB][4 * Hh];                     // gate pre-activations
    __shared__ float sh_x[EPB];                             // fed-back output

    const int r    = threadIdx.x;        // gate row 0..127
    const int lane = r & 31;
    const int wid  = r >> 5;             // warp == element it owns in combine phase
    const int b0   = blockIdx.x * EPB;

    // ---- Load all weights into registers (packed pairs along k) ----
    const float wih1 = W_ih1[r];
    const float bb1  = b_ih1[r] + b_hh1[r];
    const float bb2  = b_ih2[r] + b_hh2[r];
    const float wlin = W_lin[lane];
    const float blin = b_lin[0];

    u64 whh1p[Hh / 2], wih2p[Hh / 2], whh2p[Hh / 2];
    {
        const u64* p1 = (const u64*)(W_hh1 + r * Hh);  // rows are 128B -> 8B aligned
        const u64* p2 = (const u64*)(W_ih2 + r * Hh);
        const u64* p3 = (const u64*)(W_hh2 + r * Hh);
#pragma unroll
        for (int i = 0; i < Hh / 2; i++) { whh1p[i] = p1[i]; wih2p[i] = p2[i]; whh2p[i] = p3[i]; }
    }

    // ---- Stage input rows into SMEM (coalesced-ish, once) ----
#pragma unroll
    for (int e = 0; e < EPB; e++)
        for (int t = r; t < TIN; t += 128)
            sh_in[e][t] = input[(b0 + e) * TIN + t];

    // ---- Zero initial state; c-states live in registers of the owning thread ----
    {
        int e = wid, j = lane;
        sh_h1[e][j] = 0.0f;
        sh_h2[e][j] = 0.0f;
    }
    float c1 = 0.0f, c2 = 0.0f;   // owned by thread (e=wid, j=lane)
    __syncthreads();

    for (int t = 0; t < STEPS; t++) {
        // ======== Layer 1 gate pre-activations: z1_r = wih1*x + W_hh1[r,:]@h1 + b1 ========
        float z1[EPB];
#pragma unroll
        for (int e = 0; e < EPB; e++) {
            float x = (t < TIN) ? sh_in[e][t] : sh_x[e];
            u64 a0 = 0ull, a1 = 0ull;
            const ulonglong2* hp = (const ulonglong2*)sh_h1[e];  // broadcast LDS.128
#pragma unroll
            for (int i = 0; i < 8; i++) {
                ulonglong2 hv = hp[i];
                a0 = fma2(whh1p[2 * i],     hv.x, a0);
                a1 = fma2(whh1p[2 * i + 1], hv.y, a1);
            }
            z1[e] = fmaf(wih1, x, bb1) + ((f2lo(a0) + f2hi(a0)) + (f2lo(a1) + f2hi(a1)));
        }
#pragma unroll
        for (int e = 0; e < EPB; e++) sh_z[e][r] = z1[e];
        __syncthreads();

        // ======== Layer 1 combine: thread (wid, lane) updates h1/c1 of its unit ========
        {
            const int e = wid, j = lane;
            float zi = sh_z[e][j], zf = sh_z[e][Hh + j];
            float zg = sh_z[e][2 * Hh + j], zo = sh_z[e][3 * Hh + j];
            float cn = sigm(zf) * c1 + sigm(zi) * tanh_(zg);
            c1 = cn;
            sh_h1[e][j] = sigm(zo) * tanh_(cn);
        }
        __syncthreads();

        // ======== Layer 2: z2_r = W_ih2[r,:]@h1_new + W_hh2[r,:]@h2 + b2 ========
        float z2[EPB];
#pragma unroll
        for (int e = 0; e < EPB; e++) {
            u64 a0 = 0ull, a1 = 0ull, a2 = 0ull, a3 = 0ull;
            const ulonglong2* h1p = (const ulonglong2*)sh_h1[e];
            const ulonglong2* h2p = (const ulonglong2*)sh_h2[e];
#pragma unroll
            for (int i = 0; i < 8; i++) {
                ulonglong2 hv1 = h1p[i];
                ulonglong2 hv2 = h2p[i];
                a0 = fma2(wih2p[2 * i],     hv1.x, a0);
                a1 = fma2(wih2p[2 * i + 1], hv1.y, a1);
                a2 = fma2(whh2p[2 * i],     hv2.x, a2);
                a3 = fma2(whh2p[2 * i + 1], hv2.y, a3);
            }
            z2[e] = bb2 + ((f2lo(a0) + f2hi(a0)) + (f2lo(a1) + f2hi(a1)))
                        + ((f2lo(a2) + f2hi(a2)) + (f2lo(a3) + f2hi(a3)));
        }
#pragma unroll
        for (int e = 0; e < EPB; e++) sh_z[e][r] = z2[e];
        __syncthreads();

        // ======== Layer 2 combine + linear head + feedback ========
        {
            const int e = wid, j = lane;
            float zi = sh_z[e][j], zf = sh_z[e][Hh + j];
            float zg = sh_z[e][2 * Hh + j], zo = sh_z[e][3 * Hh + j];
            float cn = sigm(zf) * c2 + sigm(zi) * tanh_(zg);
            c2 = cn;
            float hn = sigm(zo) * tanh_(cn);
            sh_h2[e][j] = hn;

            // out[e] = W_lin @ h2_new + b_lin  (warp reduction)
            float p = wlin * hn;
#pragma unroll
            for (int off = 16; off; off >>= 1)
                p += __shfl_xor_sync(0xffffffffu, p, off);
            if (j == 0) {
                float o = p + blin;
                sh_x[e] = o;
                out[(size_t)(b0 + e) * STEPS + t] = o;
            }
        }
        __syncthreads();
    }
}

extern "C" void kernel_launch(void* const* d_in, const int* in_sizes, int n_in,
                              void* d_out, int out_size) {
    const float* input = (const float*)d_in[0];
    const float* W_ih1 = (const float*)d_in[1];
    const float* W_hh1 = (const float*)d_in[2];
    const float* b_ih1 = (const float*)d_in[3];
    const float* b_hh1 = (const float*)d_in[4];
    const float* W_ih2 = (const float*)d_in[5];
    const float* W_hh2 = (const float*)d_in[6];
    const float* b_ih2 = (const float*)d_in[7];
    const float* b_hh2 = (const float*)d_in[8];
    const float* W_lin = (const float*)d_in[9];
    const float* b_lin = (const float*)d_in[10];
    float* out = (float*)d_out;

    lstm_seq_kernel<<<BATCH / EPB, 128>>>(input, W_ih1, W_hh1, b_ih1, b_hh1,
                                          W_ih2, W_hh2, b_ih2, b_hh2,
                                          W_lin, b_lin, out);
}